// round 3
// baseline (speedup 1.0000x reference)
#include <cuda_runtime.h>
#include <cstddef>

// Problem constants
constexpr int Bn = 8;
constexpr int S  = 160;
constexpr int D  = 256;
constexpr int RS = Bn * S;          // 1280 rows
constexpr int P  = S * (S - 1) / 2; // 12720 pairs

// Scratch: xa = x@Wi + bias, xb = x@Wj   (allocation-free __device__ globals)
__device__ float g_xa[RS * D];
__device__ float g_xb[RS * D];

// ---------------------------------------------------------------------------
// Kernel 1: dual GEMM.  xa = x @ W[:D] + b,  xb = x @ W[D:].
// Grid: (RS/TM, 2) ; block 128 threads, each thread owns one output column
// within a 128-wide half. x tile (TM rows) staged in shared memory.
// ---------------------------------------------------------------------------
constexpr int TM = 16;

__global__ __launch_bounds__(128) void gemm_kernel(
    const float* __restrict__ x,
    const float* __restrict__ W,
    const float* __restrict__ bias)
{
    __shared__ float xs[TM][D];   // 16 KB

    const int r0  = blockIdx.x * TM;
    const int c0  = blockIdx.y * 128;
    const int tid = threadIdx.x;

    // stage x tile (TM x D) as float4
    const float4* xsrc = reinterpret_cast<const float4*>(x + (size_t)r0 * D);
    float4* xs4 = reinterpret_cast<float4*>(&xs[0][0]);
    #pragma unroll
    for (int k = tid; k < TM * D / 4; k += 128) xs4[k] = xsrc[k];
    __syncthreads();

    const int e = c0 + tid;
    const float bv = bias[e];

    float acc[TM], acc2[TM];
    #pragma unroll
    for (int r = 0; r < TM; r++) { acc[r] = bv; acc2[r] = 0.0f; }

    const float* W1 = W + e;             // Wi column e
    const float* W2 = W + (size_t)D * D + e; // Wj column e

    #pragma unroll 4
    for (int d = 0; d < D; d++) {
        const float w1 = W1[(size_t)d * D];
        const float w2 = W2[(size_t)d * D];
        #pragma unroll
        for (int r = 0; r < TM; r++) {
            const float xv = xs[r][d];
            acc[r]  = fmaf(xv, w1, acc[r]);
            acc2[r] = fmaf(xv, w2, acc2[r]);
        }
    }

    #pragma unroll
    for (int r = 0; r < TM; r++) {
        g_xa[(size_t)(r0 + r) * D + e] = acc[r];
        g_xb[(size_t)(r0 + r) * D + e] = acc2[r];
    }
}

// ---------------------------------------------------------------------------
// Kernel 2: pairwise expansion, tiled 16x16 over (i,j).
// Grid: (55 triangle tiles, Bn) ; block 256 threads (8 warps).
// Each block stages 16 xa rows + 16 xb rows in smem (padded, conflict-free),
// then each warp streams one pair at a time: 256 floats = 2 STG.128 / lane.
// Consecutive j -> consecutive p -> fully coalesced contiguous stores.
// ---------------------------------------------------------------------------
constexpr int TI = 16;
constexpr int TJ = 16;
constexpr int TILES_PER_DIM = S / TI;         // 10
constexpr int NTILES = TILES_PER_DIM * (TILES_PER_DIM + 1) / 2; // 55
constexpr int ROW4 = D / 4;                    // 64 float4 per row
constexpr int PAD4 = ROW4 + 2;                 // 66 -> 8-bank shift per row

__global__ __launch_bounds__(256) void expand_kernel(float* __restrict__ out)
{
    __shared__ float4 xa_s[TI * PAD4];
    __shared__ float4 xb_s[TJ * PAD4];

    // map linear tile index -> (ti, tj) in upper triangle (incl. diagonal)
    int rem = blockIdx.x;
    int ti = 0;
    while (rem >= TILES_PER_DIM - ti) { rem -= TILES_PER_DIM - ti; ti++; }
    const int tj = ti + rem;

    const int b  = blockIdx.y;
    const int i0 = ti * TI;
    const int j0 = tj * TJ;
    const int tid = threadIdx.x;

    const float4* xa4 = reinterpret_cast<const float4*>(g_xa);
    const float4* xb4 = reinterpret_cast<const float4*>(g_xb);

    // stage tiles: 16 rows x 64 float4 each
    #pragma unroll
    for (int k = tid; k < TI * ROW4; k += 256) {
        const int r = k >> 6, c = k & 63;
        xa_s[r * PAD4 + c] = xa4[(size_t)(b * S + i0 + r) * ROW4 + c];
        xb_s[r * PAD4 + c] = xb4[(size_t)(b * S + j0 + r) * ROW4 + c];
    }
    __syncthreads();

    const int warp = tid >> 5;
    const int lane = tid & 31;
    float4* out4 = reinterpret_cast<float4*>(out);

    for (int pp = warp; pp < TI * TJ; pp += 8) {
        const int ii = pp >> 4;
        const int jj = pp & 15;
        const int i = i0 + ii;
        const int j = j0 + jj;
        if (j <= i) continue;

        // p = offset(i) + (j - i - 1),  offset(i) = (2S-1-i)*i/2
        const int p = ((2 * S - 1 - i) * i) / 2 + (j - i - 1);
        float4* dst = out4 + ((size_t)b * P + p) * ROW4;

        const float4 a0 = xa_s[ii * PAD4 + lane];
        const float4 a1 = xa_s[ii * PAD4 + 32 + lane];
        const float4 c0 = xb_s[jj * PAD4 + lane];
        const float4 c1 = xb_s[jj * PAD4 + 32 + lane];

        float4 r0, r1;
        r0.x = a0.x + c0.x; r0.y = a0.y + c0.y;
        r0.z = a0.z + c0.z; r0.w = a0.w + c0.w;
        r1.x = a1.x + c1.x; r1.y = a1.y + c1.y;
        r1.z = a1.z + c1.z; r1.w = a1.w + c1.w;

        dst[lane]      = r0;
        dst[lane + 32] = r1;
    }
}

// ---------------------------------------------------------------------------
extern "C" void kernel_launch(void* const* d_in, const int* in_sizes, int n_in,
                              void* d_out, int out_size)
{
    const float* x    = (const float*)d_in[0];   // (8,160,256) f32
    const float* W    = (const float*)d_in[1];   // (512,256)   f32
    const float* bias = (const float*)d_in[2];   // (256,)      f32
    float* out = (float*)d_out;                  // (8,12720,256) f32

    dim3 ggrid(RS / TM, 2);
    gemm_kernel<<<ggrid, 128>>>(x, W, bias);

    dim3 egrid(NTILES, Bn);
    expand_kernel<<<egrid, 256>>>(out);
}

// round 5
// speedup vs baseline: 1.9332x; 1.9332x over previous
#include <cuda_runtime.h>
#include <cstddef>

// Problem constants
constexpr int Bn = 8;
constexpr int S  = 160;
constexpr int D  = 256;
constexpr int RS = Bn * S;           // 1280 rows of x (flattened)
constexpr int P  = S * (S - 1) / 2;  // 12720 pairs

// Scratch (allocation-free __device__ globals):
// g_xa = x@Wi + bias, g_xb = x@Wj
__device__ float g_xa[RS * D];
__device__ float g_xb[RS * D];

// ---------------------------------------------------------------------------
// Packed f32x2 helpers (Blackwell FFMA2 — only reachable via PTX fma.rn.f32x2)
// ---------------------------------------------------------------------------
__device__ __forceinline__ void ffma2(unsigned long long& d,
                                      unsigned long long a,
                                      unsigned long long b) {
    asm("fma.rn.f32x2 %0, %1, %2, %0;" : "+l"(d) : "l"(a), "l"(b));
}
__device__ __forceinline__ unsigned long long dup2(float x) {
    unsigned long long r;
    asm("mov.b64 %0, {%1, %1};" : "=l"(r) : "r"(__float_as_uint(x)));
    return r;
}
union F2U { unsigned long long u; float2 f; };
__device__ __forceinline__ unsigned long long as_u64(float2 v) { F2U t; t.f = v; return t.u; }
__device__ __forceinline__ float2 as_f2(unsigned long long v)  { F2U t; t.u = v; return t.f; }

// ---------------------------------------------------------------------------
// Kernel 1: dual GEMM as one M=1280, N=512 (Wi cols | Wj cols), K=256 GEMM.
// BM=64, BN=32, BK=16, 128 threads. Thread micro-tile 2 rows x 8 cols held as
// 8 packed f32x2 accumulators -> 8 FFMA2 per k-step per thread.
// x tile stored TRANSPOSED in smem (xs[k][m]) so A-operand is one LDS.64.
// Double-buffered smem, global prefetch into registers.
// ---------------------------------------------------------------------------
constexpr int BM = 64, BN = 32, BK = 16;
constexpr int NT = D / BK;  // 16 k-tiles

__global__ __launch_bounds__(128) void gemm_kernel(
    const float* __restrict__ x,
    const float* __restrict__ W,
    const float* __restrict__ bias)
{
    __shared__ float xs[2][BK][BM + 2];                 // transposed x tile
    __shared__ __align__(16) float ws[2][BK][BN + 4];   // W tile

    const int t  = threadIdx.x;
    const int r0 = blockIdx.x * BM;
    const int n0 = blockIdx.y * BN;
    const bool half = (n0 >= D);          // false -> Wi/g_xa, true -> Wj/g_xb
    const int c0 = n0 & (D - 1);          // column within the half
    const int wrowbase = half ? D : 0;    // W row offset (Wj starts at row D)

    const float4* x4 = reinterpret_cast<const float4*>(x);
    const float4* W4 = reinterpret_cast<const float4*>(W);

    // compute mapping: 32 row-pairs x 4 col-groups
    const int mt = t & 31;   // rows 2*mt, 2*mt+1
    const int nt = t >> 5;   // cols nt*8 .. nt*8+7

    // staging mapping
    const int xr = t >> 2, xf = t & 3;   // x: rows xr / xr+32, f4-chunk xf
    const int wr = t >> 3, wc = t & 7;   // W: row wr, f4-chunk wc

    unsigned long long acc[2][4];
    #pragma unroll
    for (int r = 0; r < 2; r++)
        #pragma unroll
        for (int c = 0; c < 4; c++) acc[r][c] = 0ull;

    float4 xreg0, xreg1, wreg;

    // prefetch tile 0
    xreg0 = x4[(size_t)(r0 + xr)      * 64 + 0 * 4 + xf];
    xreg1 = x4[(size_t)(r0 + 32 + xr) * 64 + 0 * 4 + xf];
    wreg  = W4[(size_t)(wrowbase + 0 * BK + wr) * 64 + (c0 >> 2) + wc];

    // store tile 0 (x transposed)
    xs[0][xf * 4 + 0][xr]      = xreg0.x;
    xs[0][xf * 4 + 1][xr]      = xreg0.y;
    xs[0][xf * 4 + 2][xr]      = xreg0.z;
    xs[0][xf * 4 + 3][xr]      = xreg0.w;
    xs[0][xf * 4 + 0][32 + xr] = xreg1.x;
    xs[0][xf * 4 + 1][32 + xr] = xreg1.y;
    xs[0][xf * 4 + 2][32 + xr] = xreg1.z;
    xs[0][xf * 4 + 3][32 + xr] = xreg1.w;
    *reinterpret_cast<float4*>(&ws[0][wr][wc * 4]) = wreg;
    __syncthreads();

    #pragma unroll 1
    for (int kt = 0; kt < NT; kt++) {
        const int cur = kt & 1;
        const int nxt = cur ^ 1;

        if (kt + 1 < NT) {  // prefetch next tile into registers
            xreg0 = x4[(size_t)(r0 + xr)      * 64 + (kt + 1) * 4 + xf];
            xreg1 = x4[(size_t)(r0 + 32 + xr) * 64 + (kt + 1) * 4 + xf];
            wreg  = W4[(size_t)(wrowbase + (kt + 1) * BK + wr) * 64 + (c0 >> 2) + wc];
        }

        // compute on current buffer
        #pragma unroll
        for (int k = 0; k < BK; k++) {
            const float2 a2 = *reinterpret_cast<const float2*>(&xs[cur][k][2 * mt]);
            const unsigned long long pa0 = dup2(a2.x);
            const unsigned long long pa1 = dup2(a2.y);
            const float* wrow = &ws[cur][k][nt * 8];
            const unsigned long long w0 = as_u64(*reinterpret_cast<const float2*>(wrow + 0));
            const unsigned long long w1 = as_u64(*reinterpret_cast<const float2*>(wrow + 2));
            const unsigned long long w2 = as_u64(*reinterpret_cast<const float2*>(wrow + 4));
            const unsigned long long w3 = as_u64(*reinterpret_cast<const float2*>(wrow + 6));
            ffma2(acc[0][0], pa0, w0); ffma2(acc[0][1], pa0, w1);
            ffma2(acc[0][2], pa0, w2); ffma2(acc[0][3], pa0, w3);
            ffma2(acc[1][0], pa1, w0); ffma2(acc[1][1], pa1, w1);
            ffma2(acc[1][2], pa1, w2); ffma2(acc[1][3], pa1, w3);
        }

        if (kt + 1 < NT) {  // store next tile, one sync per iteration
            xs[nxt][xf * 4 + 0][xr]      = xreg0.x;
            xs[nxt][xf * 4 + 1][xr]      = xreg0.y;
            xs[nxt][xf * 4 + 2][xr]      = xreg0.z;
            xs[nxt][xf * 4 + 3][xr]      = xreg0.w;
            xs[nxt][xf * 4 + 0][32 + xr] = xreg1.x;
            xs[nxt][xf * 4 + 1][32 + xr] = xreg1.y;
            xs[nxt][xf * 4 + 2][32 + xr] = xreg1.z;
            xs[nxt][xf * 4 + 3][32 + xr] = xreg1.w;
            *reinterpret_cast<float4*>(&ws[nxt][wr][wc * 4]) = wreg;
            __syncthreads();
        }
    }

    // epilogue: add bias on the Wi half, write to g_xa / g_xb
    const int cc = c0 + nt * 8;
    float bv[8];
    #pragma unroll
    for (int c = 0; c < 8; c++) bv[c] = 0.0f;
    if (!half) {
        const float4 b0 = *reinterpret_cast<const float4*>(&bias[cc]);
        const float4 b1 = *reinterpret_cast<const float4*>(&bias[cc + 4]);
        bv[0] = b0.x; bv[1] = b0.y; bv[2] = b0.z; bv[3] = b0.w;
        bv[4] = b1.x; bv[5] = b1.y; bv[6] = b1.z; bv[7] = b1.w;
    }
    float* dst = half ? g_xb : g_xa;
    #pragma unroll
    for (int rr = 0; rr < 2; rr++) {
        const int row = r0 + 2 * mt + rr;
        float o[8];
        #pragma unroll
        for (int c = 0; c < 4; c++) {
            const float2 f = as_f2(acc[rr][c]);
            o[2 * c]     = f.x + bv[2 * c];
            o[2 * c + 1] = f.y + bv[2 * c + 1];
        }
        *reinterpret_cast<float4*>(&dst[(size_t)row * D + cc])     =
            make_float4(o[0], o[1], o[2], o[3]);
        *reinterpret_cast<float4*>(&dst[(size_t)row * D + cc + 4]) =
            make_float4(o[4], o[5], o[6], o[7]);
    }
}

// ---------------------------------------------------------------------------
// Kernel 2: pairwise expansion, 16x16 (i,j) tiles, D split in halves.
// Grid: (55 triangle tiles, Bn, 2) = 880 blocks -> whole grid resident in one
// wave (~6 blocks/SM, smem 16KB). Each warp emits one pair-half per iter:
// 2 LDS.128 + 1 STG.128 per lane, stores fully contiguous per warp.
// ---------------------------------------------------------------------------
constexpr int TI  = 16;
constexpr int TPD = S / TI;                      // 10
constexpr int NTILES = TPD * (TPD + 1) / 2;      // 55

__global__ __launch_bounds__(256) void expand_kernel(float* __restrict__ out)
{
    __shared__ float4 sa[TI][32];
    __shared__ float4 sb[TI][32];

    // linear tile index -> (ti, tj) upper triangle incl. diagonal
    int rem = blockIdx.x, ti = 0;
    while (rem >= TPD - ti) { rem -= TPD - ti; ti++; }
    const int tj = ti + rem;

    const int b   = blockIdx.y;
    const int h   = blockIdx.z;    // which half of D
    const int i0  = ti * TI;
    const int j0  = tj * TI;
    const int tid = threadIdx.x;

    const float4* xa4 = reinterpret_cast<const float4*>(g_xa);
    const float4* xb4 = reinterpret_cast<const float4*>(g_xb);

    // stage 16 half-rows from each of xa, xb (32 float4 per half-row)
    #pragma unroll
    for (int q = 0; q < 2; q++) {
        const int k = tid + q * 256;
        const int r = k >> 5, c = k & 31;
        sa[r][c] = xa4[(size_t)(b * S + i0 + r) * 64 + h * 32 + c];
        sb[r][c] = xb4[(size_t)(b * S + j0 + r) * 64 + h * 32 + c];
    }
    __syncthreads();

    const int warp = tid >> 5;
    const int lane = tid & 31;
    float4* out4 = reinterpret_cast<float4*>(out);

    #pragma unroll 4
    for (int pp = warp; pp < TI * TI; pp += 8) {
        const int ii = pp >> 4;
        const int jj = pp & 15;
        const int i = i0 + ii;
        const int j = j0 + jj;
        if (j <= i) continue;

        int p = ((2 * S - 1 - i) * i) >> 1;
        p += j - i - 1;

        const float4 a = sa[ii][lane];
        const float4 c = sb[jj][lane];
        float4 v;
        v.x = a.x + c.x; v.y = a.y + c.y;
        v.z = a.z + c.z; v.w = a.w + c.w;
        out4[((size_t)b * P + p) * 64 + h * 32 + lane] = v;
    }
}

// ---------------------------------------------------------------------------
extern "C" void kernel_launch(void* const* d_in, const int* in_sizes, int n_in,
                              void* d_out, int out_size)
{
    const float* x    = (const float*)d_in[0];   // (8,160,256) f32
    const float* W    = (const float*)d_in[1];   // (512,256)   f32
    const float* bias = (const float*)d_in[2];   // (256,)      f32
    float* out = (float*)d_out;                  // (8,12720,256) f32

    gemm_kernel<<<dim3(RS / BM, 2 * D / BN), 128>>>(x, W, bias);
    expand_kernel<<<dim3(NTILES, Bn, 2), 256>>>(out);
}